// round 2
// baseline (speedup 1.0000x reference)
#include <cuda_runtime.h>
#include <cuda_bf16.h>
#include <math.h>

#define BATCH 16
#define SEQ   2048
#define DE    256
#define DA    64
#define MTOT  (BATCH*SEQ)   // 32768

// ---------------- scratch (no allocations allowed) ----------------
__device__ float g_q[MTOT * DA];     // 8 MB
__device__ float g_k[MTOT * DA];     // 8 MB
__device__ float g_v[MTOT * DE];     // 32 MB
__device__ float g_attn[MTOT * DE];  // 32 MB
__device__ float g_h[MTOT * DE];     // 32 MB
__device__ float g_sum[DE];
__device__ float g_sumsq[DE];

// ---------------- generic tiled GEMM: C[M,Nc] = A[M,256] @ W[256,Nc] + bias ----
// BM=64, BN=64, BK=32, 256 threads, 4x4 micro-tile
__global__ void gemm_bias_kernel(const float* __restrict__ A,
                                 const float* __restrict__ W,
                                 const float* __restrict__ bias,
                                 float* __restrict__ C, int Ncols) {
    __shared__ float As[32][65];   // transposed A tile, padded
    __shared__ float Ws[32][64];
    const int bm = blockIdx.x * 64;
    const int bn = blockIdx.y * 64;
    const int tid = threadIdx.x;
    const int tx = tid & 15, ty = tid >> 4;

    float c[4][4] = {};

    for (int k0 = 0; k0 < 256; k0 += 32) {
        #pragma unroll
        for (int i = 0; i < 8; i++) {
            int idx = tid + i * 256;          // 64x32 = 2048 elems
            int m = idx >> 5, kk = idx & 31;
            As[kk][m] = A[(size_t)(bm + m) * 256 + k0 + kk];
        }
        #pragma unroll
        for (int i = 0; i < 8; i++) {
            int idx = tid + i * 256;          // 32x64
            int kk = idx >> 6, n = idx & 63;
            Ws[kk][n] = W[(size_t)(k0 + kk) * Ncols + bn + n];
        }
        __syncthreads();
        #pragma unroll 8
        for (int kk = 0; kk < 32; kk++) {
            float a[4], b[4];
            #pragma unroll
            for (int i = 0; i < 4; i++) { a[i] = As[kk][ty * 4 + i]; b[i] = Ws[kk][tx * 4 + i]; }
            #pragma unroll
            for (int i = 0; i < 4; i++)
                #pragma unroll
                for (int j = 0; j < 4; j++)
                    c[i][j] += a[i] * b[j];
        }
        __syncthreads();
    }
    const float4 b4 = ((const float4*)(bias + bn))[tx];
    #pragma unroll
    for (int i = 0; i < 4; i++) {
        float4 o;
        o.x = c[i][0] + b4.x; o.y = c[i][1] + b4.y;
        o.z = c[i][2] + b4.z; o.w = c[i][3] + b4.w;
        *(float4*)&C[(size_t)(bm + ty * 4 + i) * Ncols + bn + tx * 4] = o;
    }
}

// ---------------- flash attention: 64 queries x 64 keys per tile ----------------
// grid = (32 q-tiles, 16 batches), 256 threads
// smem floats: sQ 64*65 | sK 64*65 | sS 64*65 | sMx 64 | sL 64 | sFac 64 | sV 64*64 float4
#define ATTN_SMEM_BYTES ((3*64*65 + 3*64)*4 + 64*64*16)

__global__ void attn_kernel(const float* __restrict__ q,
                            const float* __restrict__ k,
                            const float* __restrict__ v,
                            float* __restrict__ out) {
    extern __shared__ float sm[];
    float* sQ  = sm;
    float* sK  = sQ + 64 * 65;
    float* sS  = sK + 64 * 65;
    float* sMx = sS + 64 * 65;
    float* sL  = sMx + 64;
    float* sFac = sL + 64;
    float4* sV = (float4*)(sFac + 64);   // [64 keys][64 float4] = [64][256 floats]

    const int tid = threadIdx.x;
    const int b = blockIdx.y;
    const int q0 = blockIdx.x * 64;
    const float* qb = q + ((size_t)b * SEQ + q0) * DA;
    const float* kb = k + (size_t)b * SEQ * DA;
    const float* vb = v + (size_t)b * SEQ * DE;

    // load Q tile [64][64] padded to 65
    #pragma unroll
    for (int i = 0; i < 16; i++) {
        int idx = tid + i * 256;
        int r = idx >> 6, c = idx & 63;
        sQ[r * 65 + c] = qb[(size_t)r * 64 + c];
    }
    if (tid < 64) { sMx[tid] = -1e30f; sL[tid] = 0.f; }

    // O accumulator mapping: qq = tid&63 (warp = 32 consecutive queries),
    // txd = tid>>6 selects a 64-dim block -> V smem reads fully broadcast.
    const int qq = tid & 63;
    const int txd = tid >> 6;
    float4 acc[16];
    #pragma unroll
    for (int i = 0; i < 16; i++) acc[i] = make_float4(0.f, 0.f, 0.f, 0.f);

    // S-compute mapping: 16x16 thread grid, 4x4 scores each
    const int sx = tid & 15, sy = tid >> 4;

    __syncthreads();

    for (int kt = 0; kt < SEQ; kt += 64) {
        // load K tile [64][64]
        #pragma unroll
        for (int i = 0; i < 16; i++) {
            int idx = tid + i * 256;
            int r = idx >> 6, c = idx & 63;
            sK[r * 65 + c] = kb[(size_t)(kt + r) * 64 + c];
        }
        // load V tile [64][256] as float4
        const float4* vb4 = (const float4*)(vb + (size_t)kt * DE);
        #pragma unroll
        for (int i = 0; i < 16; i++) {
            int idx = tid + i * 256;
            sV[idx] = vb4[idx];
        }
        __syncthreads();

        // S = (Q @ K^T) / 64
        {
            float c[4][4] = {};
            #pragma unroll 8
            for (int kk = 0; kk < 64; kk++) {
                float a[4], bb[4];
                #pragma unroll
                for (int i = 0; i < 4; i++) {
                    a[i]  = sQ[(sy * 4 + i) * 65 + kk];
                    bb[i] = sK[(sx * 4 + i) * 65 + kk];
                }
                #pragma unroll
                for (int i = 0; i < 4; i++)
                    #pragma unroll
                    for (int j = 0; j < 4; j++)
                        c[i][j] += a[i] * bb[j];
            }
            #pragma unroll
            for (int i = 0; i < 4; i++)
                #pragma unroll
                for (int j = 0; j < 4; j++)
                    sS[(sy * 4 + i) * 65 + sx * 4 + j] = c[i][j] * (1.f / 64.f);
        }
        __syncthreads();

        // online softmax per row (threads 0..63)
        if (tid < 64) {
            float mold = sMx[tid];
            float tm = mold;
            float* row = sS + tid * 65;
            #pragma unroll 8
            for (int j = 0; j < 64; j++) tm = fmaxf(tm, row[j]);
            float fac = __expf(mold - tm);
            float s = 0.f;
            #pragma unroll 8
            for (int j = 0; j < 64; j++) {
                float p = __expf(row[j] - tm);
                row[j] = p;
                s += p;
            }
            sMx[tid] = tm;
            sL[tid] = sL[tid] * fac + s;
            sFac[tid] = fac;
        }
        __syncthreads();

        // rescale + O += P @ V
        {
            float fac = sFac[qq];
            #pragma unroll
            for (int i = 0; i < 16; i++) {
                acc[i].x *= fac; acc[i].y *= fac; acc[i].z *= fac; acc[i].w *= fac;
            }
            const float* prow = sS + qq * 65;
            const float4* vbase = sV + txd * 16;
            #pragma unroll 2
            for (int j = 0; j < 64; j++) {
                float p = prow[j];
                const float4* vr = vbase + j * 64;
                #pragma unroll
                for (int i = 0; i < 16; i++) {
                    float4 vv = vr[i];
                    acc[i].x += p * vv.x; acc[i].y += p * vv.y;
                    acc[i].z += p * vv.z; acc[i].w += p * vv.w;
                }
            }
        }
        __syncthreads();
    }

    const float inv = 1.f / sL[qq];
    float4* outp = (float4*)(out + ((size_t)b * SEQ + q0 + qq) * DE + txd * 64);
    #pragma unroll
    for (int i = 0; i < 16; i++) {
        float4 o = acc[i];
        o.x *= inv; o.y *= inv; o.z *= inv; o.w *= inv;
        outp[i] = o;
    }
}

// ---------------- BatchNorm pieces ----------------
__global__ void bn_zero_kernel() {
    int t = threadIdx.x;
    g_sum[t] = 0.f;
    g_sumsq[t] = 0.f;
}

__global__ void bn_stats_kernel(const float* __restrict__ h) {
    const int c = threadIdx.x;         // channel
    const int r0 = blockIdx.x * 128;   // 256 blocks x 128 rows
    float s = 0.f, s2 = 0.f;
    #pragma unroll 4
    for (int r = 0; r < 128; r++) {
        float x = h[(size_t)(r0 + r) * DE + c];
        s += x;
        s2 += x * x;
    }
    atomicAdd(&g_sum[c], s);
    atomicAdd(&g_sumsq[c], s2);
}

__global__ void bn_finalize_kernel(const float* __restrict__ h,
                                   const float* __restrict__ x,
                                   const float* __restrict__ gamma,
                                   const float* __restrict__ beta,
                                   float* __restrict__ y) {
    const int idx = blockIdx.x * 256 + threadIdx.x;   // float4 index
    const int c0 = (idx * 4) & 255;
    const float invM = 1.f / (float)MTOT;
    float4 hv = ((const float4*)h)[idx];
    float4 xv = ((const float4*)x)[idx];
    float r[4];
    float hvv[4] = {hv.x, hv.y, hv.z, hv.w};
    float xvv[4] = {xv.x, xv.y, xv.z, xv.w};
    #pragma unroll
    for (int u = 0; u < 4; u++) {
        int c = c0 + u;
        float mean = g_sum[c] * invM;
        float var = g_sumsq[c] * invM - mean * mean;
        float rs = rsqrtf(var + 1e-5f);
        float val = (hvv[u] - mean) * rs * gamma[c] + beta[c];
        r[u] = fmaxf(val, 0.f) + xvv[u];
    }
    float4 o = {r[0], r[1], r[2], r[3]};
    ((float4*)y)[idx] = o;
}

// ---------------- launch ----------------
extern "C" void kernel_launch(void* const* d_in, const int* in_sizes, int n_in,
                              void* d_out, int out_size) {
    const float* x     = (const float*)d_in[0];
    const float* Wq    = (const float*)d_in[1];
    const float* bq    = (const float*)d_in[2];
    const float* Wk    = (const float*)d_in[3];
    const float* bk    = (const float*)d_in[4];
    const float* Wv    = (const float*)d_in[5];
    const float* bv    = (const float*)d_in[6];
    const float* Wl    = (const float*)d_in[7];
    const float* bl    = (const float*)d_in[8];
    const float* gamma = (const float*)d_in[9];
    const float* beta  = (const float*)d_in[10];
    float* out = (float*)d_out;

    float *pq, *pk, *pv, *pattn, *ph;
    cudaGetSymbolAddress((void**)&pq, g_q);
    cudaGetSymbolAddress((void**)&pk, g_k);
    cudaGetSymbolAddress((void**)&pv, g_v);
    cudaGetSymbolAddress((void**)&pattn, g_attn);
    cudaGetSymbolAddress((void**)&ph, g_h);

    cudaFuncSetAttribute(attn_kernel, cudaFuncAttributeMaxDynamicSharedMemorySize,
                         ATTN_SMEM_BYTES);

    // q, k, v projections
    gemm_bias_kernel<<<dim3(MTOT / 64, 1), 256>>>(x, Wq, bq, pq, DA);
    gemm_bias_kernel<<<dim3(MTOT / 64, 1), 256>>>(x, Wk, bk, pk, DA);
    gemm_bias_kernel<<<dim3(MTOT / 64, 4), 256>>>(x, Wv, bv, pv, DE);

    // attention
    attn_kernel<<<dim3(SEQ / 64, BATCH), 256, ATTN_SMEM_BYTES>>>(pq, pk, pv, pattn);

    // h = attn @ Wl + bl
    gemm_bias_kernel<<<dim3(MTOT / 64, 4), 256>>>(pattn, Wl, bl, ph, DE);

    // batchnorm + relu + residual
    bn_zero_kernel<<<1, 256>>>();
    bn_stats_kernel<<<MTOT / 128, 256>>>(ph);
    bn_finalize_kernel<<<(MTOT * DE) / 4 / 256, 256>>>(ph, x, gamma, beta, out);
}

// round 4
// speedup vs baseline: 2.9602x; 2.9602x over previous
#include <cuda_runtime.h>
#include <cuda_bf16.h>
#include <cstdint>
#include <math.h>

#define BATCH 16
#define SEQ   2048
#define DE    256
#define DA    64
#define MTOT  (BATCH*SEQ)   // 32768

// ---------------- scratch ----------------
__device__ float g_q[MTOT * DA];      // 8 MB  (tf32-rounded)
__device__ float g_k[MTOT * DA];      // 8 MB  (tf32-rounded)
__device__ float g_v[MTOT * DE];      // 32 MB (tf32-rounded)
__device__ float g_attn[MTOT * DE];   // 32 MB
__device__ float g_h[MTOT * DE];      // 32 MB
__device__ float g_sum[DE];
__device__ float g_sumsq[DE];

// ================= helpers =================
__device__ __forceinline__ uint32_t smem_to_u32(const void* p) {
    uint32_t a;
    asm("{ .reg .u64 t; cvta.to.shared.u64 t, %1; cvt.u32.u64 %0, t; }" : "=r"(a) : "l"(p));
    return a;
}
__device__ __forceinline__ float tf32_round(float x) {
    uint32_t u;
    asm("cvt.rna.tf32.f32 %0, %1;" : "=r"(u) : "f"(x));
    return __uint_as_float(u);
}
__device__ __forceinline__ uint32_t tf32_bits(float x) {
    uint32_t u;
    asm("cvt.rna.tf32.f32 %0, %1;" : "=r"(u) : "f"(x));
    return u;
}
__device__ __forceinline__ void mma_tf32(float* c, const uint32_t* a,
                                         uint32_t b0, uint32_t b1) {
    asm volatile(
        "mma.sync.aligned.m16n8k8.row.col.f32.tf32.tf32.f32 "
        "{%0,%1,%2,%3}, {%4,%5,%6,%7}, {%8,%9}, {%0,%1,%2,%3};"
        : "+f"(c[0]), "+f"(c[1]), "+f"(c[2]), "+f"(c[3])
        : "r"(a[0]), "r"(a[1]), "r"(a[2]), "r"(a[3]), "r"(b0), "r"(b1));
}
__device__ __forceinline__ void cp_async16(uint32_t dst, const void* src) {
    asm volatile("cp.async.cg.shared.global [%0], [%1], 16;" :: "r"(dst), "l"(src));
}

// ---------------- fp32 tiled GEMM (optionally tf32-rounding the output) -----
__global__ void gemm_bias_kernel(const float* __restrict__ A,
                                 const float* __restrict__ W,
                                 const float* __restrict__ bias,
                                 float* __restrict__ C, int Ncols, int roundtf) {
    __shared__ float As[32][65];
    __shared__ float Ws[32][64];
    const int bm = blockIdx.x * 64;
    const int bn = blockIdx.y * 64;
    const int tid = threadIdx.x;
    const int tx = tid & 15, ty = tid >> 4;
    float c[4][4] = {};
    for (int k0 = 0; k0 < 256; k0 += 32) {
        #pragma unroll
        for (int i = 0; i < 8; i++) {
            int idx = tid + i * 256;
            int m = idx >> 5, kk = idx & 31;
            As[kk][m] = A[(size_t)(bm + m) * 256 + k0 + kk];
        }
        #pragma unroll
        for (int i = 0; i < 8; i++) {
            int idx = tid + i * 256;
            int kk = idx >> 6, n = idx & 63;
            Ws[kk][n] = W[(size_t)(k0 + kk) * Ncols + bn + n];
        }
        __syncthreads();
        #pragma unroll 8
        for (int kk = 0; kk < 32; kk++) {
            float a[4], b[4];
            #pragma unroll
            for (int i = 0; i < 4; i++) { a[i] = As[kk][ty * 4 + i]; b[i] = Ws[kk][tx * 4 + i]; }
            #pragma unroll
            for (int i = 0; i < 4; i++)
                #pragma unroll
                for (int j = 0; j < 4; j++)
                    c[i][j] += a[i] * b[j];
        }
        __syncthreads();
    }
    const float4 b4 = ((const float4*)(bias + bn))[tx];
    #pragma unroll
    for (int i = 0; i < 4; i++) {
        float4 o;
        o.x = c[i][0] + b4.x; o.y = c[i][1] + b4.y;
        o.z = c[i][2] + b4.z; o.w = c[i][3] + b4.w;
        if (roundtf) {
            o.x = tf32_round(o.x); o.y = tf32_round(o.y);
            o.z = tf32_round(o.z); o.w = tf32_round(o.w);
        }
        *(float4*)&C[(size_t)(bm + ty * 4 + i) * Ncols + bn + tx * 4] = o;
    }
}

// ---------------- mma.sync tf32 flash attention ----------------
// grid (16 q-tiles, 16 batches), 256 threads (8 warps x 16 queries)
// K tile [64][68] floats, V tile [64][260] floats, double buffered.
#define KSTR 68
#define VSTR 260
#define K_F  (64*KSTR)               // 4352 floats
#define V_F  (64*VSTR)               // 16640 floats
#define STG_F (K_F + V_F)            // 20992 floats
#define ATTN_SMEM (2*STG_F*4)        // 167936 bytes

__global__ void __launch_bounds__(256, 1)
attn_mma_kernel(const float* __restrict__ q,
                const float* __restrict__ k,
                const float* __restrict__ v,
                float* __restrict__ out) {
    extern __shared__ float sm[];
    const uint32_t sbase = smem_to_u32(sm);
    const int tid = threadIdx.x;
    const int lane = tid & 31, w = tid >> 5;
    const int g = lane >> 2, t = lane & 3;
    const int b = blockIdx.y;
    const int q0 = blockIdx.x * 128;

    const float* kb = k + (size_t)b * SEQ * DA;
    const float* vb = v + (size_t)b * SEQ * DE;

    // ---- preload Q A-fragments (q already tf32-rounded in memory) ----
    const float* qr0 = q + (size_t)(b * SEQ + q0 + w * 16 + g) * DA;
    const float* qr8 = qr0 + 8 * DA;
    uint32_t qa[8][4];
    #pragma unroll
    for (int ks = 0; ks < 8; ks++) {
        qa[ks][0] = __float_as_uint(qr0[ks * 8 + t]);
        qa[ks][1] = __float_as_uint(qr8[ks * 8 + t]);
        qa[ks][2] = __float_as_uint(qr0[ks * 8 + t + 4]);
        qa[ks][3] = __float_as_uint(qr8[ks * 8 + t + 4]);
    }

    float o[32][4];
    #pragma unroll
    for (int i = 0; i < 32; i++) { o[i][0] = o[i][1] = o[i][2] = o[i][3] = 0.f; }
    float rs0 = 0.f, rs1 = 0.f;

    // ---- async tile loader ----
    auto issue = [&](int tile, int stage) {
        const uint32_t kd = sbase + (uint32_t)(stage * STG_F) * 4u;
        const uint32_t vd = kd + (uint32_t)K_F * 4u;
        const float* ksrc = kb + (size_t)tile * 64 * DA;
        const float* vsrc = vb + (size_t)tile * 64 * DE;
        #pragma unroll
        for (int i = 0; i < 4; i++) {            // K: 1024 float4
            int idx = tid + i * 256;
            int r = idx >> 4, c4 = idx & 15;
            cp_async16(kd + (uint32_t)(r * KSTR + c4 * 4) * 4u, ksrc + r * 64 + c4 * 4);
        }
        #pragma unroll
        for (int i = 0; i < 16; i++) {           // V: 4096 float4
            int idx = tid + i * 256;
            int r = idx >> 6, c4 = idx & 63;
            cp_async16(vd + (uint32_t)(r * VSTR + c4 * 4) * 4u, vsrc + r * 256 + c4 * 4);
        }
    };

    issue(0, 0);
    asm volatile("cp.async.commit_group;" ::: "memory");

    for (int tile = 0; tile < SEQ / 64; tile++) {
        if (tile + 1 < SEQ / 64) {
            issue(tile + 1, (tile + 1) & 1);
            asm volatile("cp.async.commit_group;" ::: "memory");
            asm volatile("cp.async.wait_group 1;" ::: "memory");
        } else {
            asm volatile("cp.async.wait_group 0;" ::: "memory");
        }
        __syncthreads();

        const float* sK = sm + (tile & 1) * STG_F;
        const float* sV = sK + K_F;

        // ---- S = Q @ K^T (raw dot products; scale folded into exp) ----
        float c[8][4];
        #pragma unroll
        for (int nb = 0; nb < 8; nb++) c[nb][0] = c[nb][1] = c[nb][2] = c[nb][3] = 0.f;
        #pragma unroll
        for (int ks = 0; ks < 8; ks++) {
            #pragma unroll
            for (int nb = 0; nb < 8; nb++) {
                const float* kr = sK + (nb * 8 + g) * KSTR + ks * 8 + t;
                uint32_t b0 = __float_as_uint(kr[0]);
                uint32_t b1 = __float_as_uint(kr[4]);
                mma_tf32(c[nb], qa[ks], b0, b1);
            }
        }

        // ---- P = exp(S/64); row sums; pack A'-fragments (a = {c0,c2,c1,c3}) ----
        uint32_t p[8][4];
        #pragma unroll
        for (int nb = 0; nb < 8; nb++) {
            float e0 = __expf(c[nb][0] * 0.015625f);
            float e1 = __expf(c[nb][1] * 0.015625f);
            float e2 = __expf(c[nb][2] * 0.015625f);
            float e3 = __expf(c[nb][3] * 0.015625f);
            rs0 += e0 + e1;
            rs1 += e2 + e3;
            p[nb][0] = tf32_bits(e0);
            p[nb][1] = tf32_bits(e2);
            p[nb][2] = tf32_bits(e1);
            p[nb][3] = tf32_bits(e3);
        }

        // ---- O += P @ V (V rows key-permuted {2t, 2t+1} to match A' layout) ----
        #pragma unroll
        for (int ks = 0; ks < 8; ks++) {
            const float* vrA = sV + (ks * 8 + 2 * t) * VSTR;      // key 2t
            const float* vrB = vrA + VSTR;                        // key 2t+1
            #pragma unroll
            for (int nb2 = 0; nb2 < 32; nb2++) {
                uint32_t b0 = __float_as_uint(vrA[nb2 * 8 + g]);
                uint32_t b1 = __float_as_uint(vrB[nb2 * 8 + g]);
                mma_tf32(o[nb2], p[ks], b0, b1);
            }
        }
        __syncthreads();
    }

    // ---- finalize: reduce row sums across the quad, scale, store ----
    rs0 += __shfl_xor_sync(0xffffffff, rs0, 1);
    rs0 += __shfl_xor_sync(0xffffffff, rs0, 2);
    rs1 += __shfl_xor_sync(0xffffffff, rs1, 1);
    rs1 += __shfl_xor_sync(0xffffffff, rs1, 2);
    const float inv0 = 1.f / rs0;
    const float inv1 = 1.f / rs1;

    float* or0 = out + (size_t)(b * SEQ + q0 + w * 16 + g) * DE;
    float* or8 = or0 + 8 * DE;
    #pragma unroll
    for (int nb2 = 0; nb2 < 32; nb2++) {
        float2 v01 = make_float2(o[nb2][0] * inv0, o[nb2][1] * inv0);
        float2 v23 = make_float2(o[nb2][2] * inv1, o[nb2][3] * inv1);
        *(float2*)&or0[nb2 * 8 + 2 * t] = v01;
        *(float2*)&or8[nb2 * 8 + 2 * t] = v23;
    }
}

// ---------------- BatchNorm pieces ----------------
__global__ void bn_zero_kernel() {
    int tidx = threadIdx.x;
    g_sum[tidx] = 0.f;
    g_sumsq[tidx] = 0.f;
}

__global__ void bn_stats_kernel(const float* __restrict__ h) {
    const int c = threadIdx.x;
    const int r0 = blockIdx.x * 128;
    float s = 0.f, s2 = 0.f;
    #pragma unroll 4
    for (int r = 0; r < 128; r++) {
        float x = h[(size_t)(r0 + r) * DE + c];
        s += x;
        s2 += x * x;
    }
    atomicAdd(&g_sum[c], s);
    atomicAdd(&g_sumsq[c], s2);
}

__global__ void bn_finalize_kernel(const float* __restrict__ h,
                                   const float* __restrict__ x,
                                   const float* __restrict__ gamma,
                                   const float* __restrict__ beta,
                                   float* __restrict__ y) {
    const int idx = blockIdx.x * 256 + threadIdx.x;
    const int c0 = (idx * 4) & 255;
    const float invM = 1.f / (float)MTOT;
    float4 hv = ((const float4*)h)[idx];
    float4 xv = ((const float4*)x)[idx];
    float r[4];
    float hvv[4] = {hv.x, hv.y, hv.z, hv.w};
    float xvv[4] = {xv.x, xv.y, xv.z, xv.w};
    #pragma unroll
    for (int u = 0; u < 4; u++) {
        int c = c0 + u;
        float mean = g_sum[c] * invM;
        float var = g_sumsq[c] * invM - mean * mean;
        float rsv = rsqrtf(var + 1e-5f);
        float val = (hvv[u] - mean) * rsv * gamma[c] + beta[c];
        r[u] = fmaxf(val, 0.f) + xvv[u];
    }
    float4 ov = {r[0], r[1], r[2], r[3]};
    ((float4*)y)[idx] = ov;
}

// ---------------- launch ----------------
extern "C" void kernel_launch(void* const* d_in, const int* in_sizes, int n_in,
                              void* d_out, int out_size) {
    const float* x     = (const float*)d_in[0];
    const float* Wq    = (const float*)d_in[1];
    const float* bq    = (const float*)d_in[2];
    const float* Wk    = (const float*)d_in[3];
    const float* bk    = (const float*)d_in[4];
    const float* Wv    = (const float*)d_in[5];
    const float* bv    = (const float*)d_in[6];
    const float* Wl    = (const float*)d_in[7];
    const float* bl    = (const float*)d_in[8];
    const float* gamma = (const float*)d_in[9];
    const float* beta  = (const float*)d_in[10];
    float* out = (float*)d_out;

    float *pq, *pk, *pv, *pattn, *ph;
    cudaGetSymbolAddress((void**)&pq, g_q);
    cudaGetSymbolAddress((void**)&pk, g_k);
    cudaGetSymbolAddress((void**)&pv, g_v);
    cudaGetSymbolAddress((void**)&pattn, g_attn);
    cudaGetSymbolAddress((void**)&ph, g_h);

    cudaFuncSetAttribute(attn_mma_kernel, cudaFuncAttributeMaxDynamicSharedMemorySize,
                         ATTN_SMEM);

    // projections (outputs tf32-rounded for the mma attention)
    gemm_bias_kernel<<<dim3(MTOT / 64, 1), 256>>>(x, Wq, bq, pq, DA, 1);
    gemm_bias_kernel<<<dim3(MTOT / 64, 1), 256>>>(x, Wk, bk, pk, DA, 1);
    gemm_bias_kernel<<<dim3(MTOT / 64, 4), 256>>>(x, Wv, bv, pv, DE, 1);

    // attention (mma.sync tf32)
    attn_mma_kernel<<<dim3(SEQ / 128, BATCH), 256, ATTN_SMEM>>>(pq, pk, pv, pattn);

    // h = attn @ Wl + bl   (full fp32)
    gemm_bias_kernel<<<dim3(MTOT / 64, 4), 256>>>(pattn, Wl, bl, ph, DE, 0);

    // batchnorm + relu + residual
    bn_zero_kernel<<<1, 256>>>();
    bn_stats_kernel<<<MTOT / 128, 256>>>(ph);
    bn_finalize_kernel<<<(MTOT * DE) / 4 / 256, 256>>>(ph, x, gamma, beta, out);
}

// round 5
// speedup vs baseline: 4.9220x; 1.6627x over previous
#include <cuda_runtime.h>
#include <cuda_bf16.h>
#include <cstdint>
#include <math.h>

#define BATCH 16
#define SEQ   2048
#define DE    256
#define DA    64
#define MTOT  (BATCH*SEQ)   // 32768

// ---------------- scratch ----------------
__device__ float g_q[MTOT * DA];      // 8 MB
__device__ float g_k[MTOT * DA];      // 8 MB
__device__ float g_v[MTOT * DE];      // 32 MB
__device__ float g_attn[MTOT * DE];   // 32 MB
__device__ float g_h[MTOT * DE];      // 32 MB
__device__ float g_sum[DE];
__device__ float g_sumsq[DE];

// ================= helpers =================
__device__ __forceinline__ uint32_t smem_to_u32(const void* p) {
    uint32_t a;
    asm("{ .reg .u64 t; cvta.to.shared.u64 t, %1; cvt.u32.u64 %0, t; }" : "=r"(a) : "l"(p));
    return a;
}
__device__ __forceinline__ uint32_t tf32_bits(float x) {
    uint32_t u;
    asm("cvt.rna.tf32.f32 %0, %1;" : "=r"(u) : "f"(x));
    return u;
}
__device__ __forceinline__ void mma_tf32(float* c, const uint32_t* a,
                                         uint32_t b0, uint32_t b1) {
    asm volatile(
        "mma.sync.aligned.m16n8k8.row.col.f32.tf32.tf32.f32 "
        "{%0,%1,%2,%3}, {%4,%5,%6,%7}, {%8,%9}, {%0,%1,%2,%3};"
        : "+f"(c[0]), "+f"(c[1]), "+f"(c[2]), "+f"(c[3])
        : "r"(a[0]), "r"(a[1]), "r"(a[2]), "r"(a[3]), "r"(b0), "r"(b1));
}
__device__ __forceinline__ void cp_async16(uint32_t dst, const void* src) {
    asm volatile("cp.async.cg.shared.global [%0], [%1], 16;" :: "r"(dst), "l"(src));
}

// ---------------- mma.sync tf32 GEMM: C[M,Nc] = A[M,256] @ W[256,Nc] + bias ----
// BM=128, BN=64, BK=32, 256 threads (8 warps), warp tile 32m x 32n.
// A smem: [128][32] floats, float4-group swizzle: group k4 stored at k4 ^ (m&7)
// W smem: [32][64]  floats, group n4 stored at n4 ^ (2*(k&3))
#define GA_F 4096          // floats per A stage
#define GW_F 2048          // floats per W stage
#define GEMM_SMEM ((2*GA_F + 2*GW_F)*4)   // 49152 bytes

__global__ void __launch_bounds__(256)
gemm_mma_kernel(const float* __restrict__ A,
                const float* __restrict__ W,
                const float* __restrict__ bias,
                float* __restrict__ C, int Ncols) {
    extern __shared__ float sm[];
    float* smA = sm;                 // 2 stages x 4096 floats
    float* smW = sm + 2 * GA_F;      // 2 stages x 2048 floats
    const uint32_t sbA = smem_to_u32(smA);
    const uint32_t sbW = smem_to_u32(smW);

    const int tid = threadIdx.x;
    const int lane = tid & 31, w = tid >> 5;
    const int g = lane >> 2, t = lane & 3;
    const int mw = w >> 1, nw = w & 1;          // warp grid 4(m) x 2(n)
    const int bm = blockIdx.x * 128;
    const int bn = blockIdx.y * 64;

    float c[2][4][4];
    #pragma unroll
    for (int mb = 0; mb < 2; mb++)
        #pragma unroll
        for (int nb = 0; nb < 4; nb++)
            c[mb][nb][0] = c[mb][nb][1] = c[mb][nb][2] = c[mb][nb][3] = 0.f;

    auto issue = [&](int chunk, int stage) {
        const int k0 = chunk * 32;
        // A: 1024 float4, 4 per thread
        #pragma unroll
        for (int i = 0; i < 4; i++) {
            int idx = tid + i * 256;
            int m = idx >> 3, k4 = idx & 7;
            cp_async16(sbA + (uint32_t)(stage * GA_F + m * 32 + (k4 ^ (m & 7)) * 4) * 4u,
                       A + (size_t)(bm + m) * 256 + k0 + k4 * 4);
        }
        // W: 512 float4, 2 per thread
        #pragma unroll
        for (int i = 0; i < 2; i++) {
            int idx = tid + i * 256;
            int kk = idx >> 4, n4 = idx & 15;
            cp_async16(sbW + (uint32_t)(stage * GW_F + kk * 64 + (n4 ^ (2 * (kk & 3))) * 4) * 4u,
                       W + (size_t)(kk) * Ncols + bn + n4 * 4);
        }
        (void)k0;
    };

    // NOTE: W rows depend on k0 — fix inside issue (k0 used for W too):
    // (lambda above uses kk only 0..31; add k0 below)
    auto issue2 = [&](int chunk, int stage) {
        const int k0 = chunk * 32;
        #pragma unroll
        for (int i = 0; i < 4; i++) {
            int idx = tid + i * 256;
            int m = idx >> 3, k4 = idx & 7;
            cp_async16(sbA + (uint32_t)(stage * GA_F + m * 32 + (k4 ^ (m & 7)) * 4) * 4u,
                       A + (size_t)(bm + m) * 256 + k0 + k4 * 4);
        }
        #pragma unroll
        for (int i = 0; i < 2; i++) {
            int idx = tid + i * 256;
            int kk = idx >> 4, n4 = idx & 15;
            cp_async16(sbW + (uint32_t)(stage * GW_F + kk * 64 + (n4 ^ (2 * (kk & 3))) * 4) * 4u,
                       W + (size_t)(k0 + kk) * Ncols + bn + n4 * 4);
        }
    };
    (void)issue;

    issue2(0, 0);
    asm volatile("cp.async.commit_group;" ::: "memory");

    for (int ch = 0; ch < 8; ch++) {
        if (ch + 1 < 8) {
            issue2(ch + 1, (ch + 1) & 1);
            asm volatile("cp.async.commit_group;" ::: "memory");
            asm volatile("cp.async.wait_group 1;" ::: "memory");
        } else {
            asm volatile("cp.async.wait_group 0;" ::: "memory");
        }
        __syncthreads();

        const float* cA = smA + (ch & 1) * GA_F;
        const float* cW = smW + (ch & 1) * GW_F;

        // fragment loads (all conflict-free by swizzle construction)
        uint32_t af[4][2][4];
        #pragma unroll
        for (int ks = 0; ks < 4; ks++) {
            #pragma unroll
            for (int mb = 0; mb < 2; mb++) {
                int r0 = mw * 32 + mb * 16 + g;
                int r8 = r0 + 8;
                int kA = ks * 8 + t;
                af[ks][mb][0] = __float_as_uint(cA[r0 * 32 + (((kA) >> 2) ^ (r0 & 7)) * 4 + (kA & 3)]);
                af[ks][mb][1] = __float_as_uint(cA[r8 * 32 + (((kA) >> 2) ^ (r8 & 7)) * 4 + (kA & 3)]);
                int kB = kA + 4;
                af[ks][mb][2] = __float_as_uint(cA[r0 * 32 + (((kB) >> 2) ^ (r0 & 7)) * 4 + (kB & 3)]);
                af[ks][mb][3] = __float_as_uint(cA[r8 * 32 + (((kB) >> 2) ^ (r8 & 7)) * 4 + (kB & 3)]);
            }
        }
        uint32_t bf[4][4][2];
        #pragma unroll
        for (int ks = 0; ks < 4; ks++) {
            #pragma unroll
            for (int nb = 0; nb < 4; nb++) {
                int n = nw * 32 + nb * 8 + g;
                int k1 = ks * 8 + t;
                int k2 = k1 + 4;
                bf[ks][nb][0] = __float_as_uint(cW[k1 * 64 + ((n >> 2) ^ (2 * (k1 & 3))) * 4 + (n & 3)]);
                bf[ks][nb][1] = __float_as_uint(cW[k2 * 64 + ((n >> 2) ^ (2 * (k2 & 3))) * 4 + (n & 3)]);
            }
        }
        #pragma unroll
        for (int ks = 0; ks < 4; ks++)
            #pragma unroll
            for (int mb = 0; mb < 2; mb++)
                #pragma unroll
                for (int nb = 0; nb < 4; nb++)
                    mma_tf32(c[mb][nb], af[ks][mb], bf[ks][nb][0], bf[ks][nb][1]);
        __syncthreads();
    }

    // epilogue: bias + store
    #pragma unroll
    for (int nb = 0; nb < 4; nb++) {
        int col = bn + nw * 32 + nb * 8 + 2 * t;
        float b0 = bias[col], b1 = bias[col + 1];
        #pragma unroll
        for (int mb = 0; mb < 2; mb++) {
            int row = bm + mw * 32 + mb * 16 + g;
            float2 v01 = make_float2(c[mb][nb][0] + b0, c[mb][nb][1] + b1);
            float2 v23 = make_float2(c[mb][nb][2] + b0, c[mb][nb][3] + b1);
            *(float2*)&C[(size_t)row * Ncols + col] = v01;
            *(float2*)&C[(size_t)(row + 8) * Ncols + col] = v23;
        }
    }
}

// ---------------- mma.sync tf32 flash attention (unchanged from R4) ----------
#define KSTR 68
#define VSTR 260
#define K_F  (64*KSTR)
#define V_F  (64*VSTR)
#define STG_F (K_F + V_F)
#define ATTN_SMEM (2*STG_F*4)

__global__ void __launch_bounds__(256, 1)
attn_mma_kernel(const float* __restrict__ q,
                const float* __restrict__ k,
                const float* __restrict__ v,
                float* __restrict__ out) {
    extern __shared__ float sm[];
    const uint32_t sbase = smem_to_u32(sm);
    const int tid = threadIdx.x;
    const int lane = tid & 31, w = tid >> 5;
    const int g = lane >> 2, t = lane & 3;
    const int b = blockIdx.y;
    const int q0 = blockIdx.x * 128;

    const float* kb = k + (size_t)b * SEQ * DA;
    const float* vb = v + (size_t)b * SEQ * DE;

    const float* qr0 = q + (size_t)(b * SEQ + q0 + w * 16 + g) * DA;
    const float* qr8 = qr0 + 8 * DA;
    uint32_t qa[8][4];
    #pragma unroll
    for (int ks = 0; ks < 8; ks++) {
        qa[ks][0] = __float_as_uint(qr0[ks * 8 + t]);
        qa[ks][1] = __float_as_uint(qr8[ks * 8 + t]);
        qa[ks][2] = __float_as_uint(qr0[ks * 8 + t + 4]);
        qa[ks][3] = __float_as_uint(qr8[ks * 8 + t + 4]);
    }

    float o[32][4];
    #pragma unroll
    for (int i = 0; i < 32; i++) { o[i][0] = o[i][1] = o[i][2] = o[i][3] = 0.f; }
    float rs0 = 0.f, rs1 = 0.f;

    auto issue = [&](int tile, int stage) {
        const uint32_t kd = sbase + (uint32_t)(stage * STG_F) * 4u;
        const uint32_t vd = kd + (uint32_t)K_F * 4u;
        const float* ksrc = kb + (size_t)tile * 64 * DA;
        const float* vsrc = vb + (size_t)tile * 64 * DE;
        #pragma unroll
        for (int i = 0; i < 4; i++) {
            int idx = tid + i * 256;
            int r = idx >> 4, c4 = idx & 15;
            cp_async16(kd + (uint32_t)(r * KSTR + c4 * 4) * 4u, ksrc + r * 64 + c4 * 4);
        }
        #pragma unroll
        for (int i = 0; i < 16; i++) {
            int idx = tid + i * 256;
            int r = idx >> 6, c4 = idx & 63;
            cp_async16(vd + (uint32_t)(r * VSTR + c4 * 4) * 4u, vsrc + r * 256 + c4 * 4);
        }
    };

    issue(0, 0);
    asm volatile("cp.async.commit_group;" ::: "memory");

    for (int tile = 0; tile < SEQ / 64; tile++) {
        if (tile + 1 < SEQ / 64) {
            issue(tile + 1, (tile + 1) & 1);
            asm volatile("cp.async.commit_group;" ::: "memory");
            asm volatile("cp.async.wait_group 1;" ::: "memory");
        } else {
            asm volatile("cp.async.wait_group 0;" ::: "memory");
        }
        __syncthreads();

        const float* sK = sm + (tile & 1) * STG_F;
        const float* sV = sK + K_F;

        float c[8][4];
        #pragma unroll
        for (int nb = 0; nb < 8; nb++) c[nb][0] = c[nb][1] = c[nb][2] = c[nb][3] = 0.f;
        #pragma unroll
        for (int ks = 0; ks < 8; ks++) {
            #pragma unroll
            for (int nb = 0; nb < 8; nb++) {
                const float* kr = sK + (nb * 8 + g) * KSTR + ks * 8 + t;
                uint32_t b0 = __float_as_uint(kr[0]);
                uint32_t b1 = __float_as_uint(kr[4]);
                mma_tf32(c[nb], qa[ks], b0, b1);
            }
        }

        uint32_t p[8][4];
        #pragma unroll
        for (int nb = 0; nb < 8; nb++) {
            float e0 = __expf(c[nb][0] * 0.015625f);
            float e1 = __expf(c[nb][1] * 0.015625f);
            float e2 = __expf(c[nb][2] * 0.015625f);
            float e3 = __expf(c[nb][3] * 0.015625f);
            rs0 += e0 + e1;
            rs1 += e2 + e3;
            p[nb][0] = tf32_bits(e0);
            p[nb][1] = tf32_bits(e2);
            p[nb][2] = tf32_bits(e1);
            p[nb][3] = tf32_bits(e3);
        }

        #pragma unroll
        for (int ks = 0; ks < 8; ks++) {
            const float* vrA = sV + (ks * 8 + 2 * t) * VSTR;
            const float* vrB = vrA + VSTR;
            #pragma unroll
            for (int nb2 = 0; nb2 < 32; nb2++) {
                uint32_t b0 = __float_as_uint(vrA[nb2 * 8 + g]);
                uint32_t b1 = __float_as_uint(vrB[nb2 * 8 + g]);
                mma_tf32(o[nb2], p[ks], b0, b1);
            }
        }
        __syncthreads();
    }

    rs0 += __shfl_xor_sync(0xffffffff, rs0, 1);
    rs0 += __shfl_xor_sync(0xffffffff, rs0, 2);
    rs1 += __shfl_xor_sync(0xffffffff, rs1, 1);
    rs1 += __shfl_xor_sync(0xffffffff, rs1, 2);
    const float inv0 = 1.f / rs0;
    const float inv1 = 1.f / rs1;

    float* or0 = out + (size_t)(b * SEQ + q0 + w * 16 + g) * DE;
    float* or8 = or0 + 8 * DE;
    #pragma unroll
    for (int nb2 = 0; nb2 < 32; nb2++) {
        float2 v01 = make_float2(o[nb2][0] * inv0, o[nb2][1] * inv0);
        float2 v23 = make_float2(o[nb2][2] * inv1, o[nb2][3] * inv1);
        *(float2*)&or0[nb2 * 8 + 2 * t] = v01;
        *(float2*)&or8[nb2 * 8 + 2 * t] = v23;
    }
}

// ---------------- BatchNorm pieces ----------------
__global__ void bn_zero_kernel() {
    int tidx = threadIdx.x;
    g_sum[tidx] = 0.f;
    g_sumsq[tidx] = 0.f;
}

__global__ void bn_stats_kernel(const float* __restrict__ h) {
    const int c = threadIdx.x;
    const int r0 = blockIdx.x * 128;
    float s = 0.f, s2 = 0.f;
    #pragma unroll 4
    for (int r = 0; r < 128; r++) {
        float x = h[(size_t)(r0 + r) * DE + c];
        s += x;
        s2 += x * x;
    }
    atomicAdd(&g_sum[c], s);
    atomicAdd(&g_sumsq[c], s2);
}

__global__ void bn_finalize_kernel(const float* __restrict__ h,
                                   const float* __restrict__ x,
                                   const float* __restrict__ gamma,
                                   const float* __restrict__ beta,
                                   float* __restrict__ y) {
    const int idx = blockIdx.x * 256 + threadIdx.x;
    const int c0 = (idx * 4) & 255;
    const float invM = 1.f / (float)MTOT;
    float4 hv = ((const float4*)h)[idx];
    float4 xv = ((const float4*)x)[idx];
    float r[4];
    float hvv[4] = {hv.x, hv.y, hv.z, hv.w};
    float xvv[4] = {xv.x, xv.y, xv.z, xv.w};
    #pragma unroll
    for (int u = 0; u < 4; u++) {
        int c = c0 + u;
        float mean = g_sum[c] * invM;
        float var = g_sumsq[c] * invM - mean * mean;
        float rsv = rsqrtf(var + 1e-5f);
        float val = (hvv[u] - mean) * rsv * gamma[c] + beta[c];
        r[u] = fmaxf(val, 0.f) + xvv[u];
    }
    float4 ov = {r[0], r[1], r[2], r[3]};
    ((float4*)y)[idx] = ov;
}

// ---------------- launch ----------------
extern "C" void kernel_launch(void* const* d_in, const int* in_sizes, int n_in,
                              void* d_out, int out_size) {
    const float* x     = (const float*)d_in[0];
    const float* Wq    = (const float*)d_in[1];
    const float* bq    = (const float*)d_in[2];
    const float* Wk    = (const float*)d_in[3];
    const float* bk    = (const float*)d_in[4];
    const float* Wv    = (const float*)d_in[5];
    const float* bv    = (const float*)d_in[6];
    const float* Wl    = (const float*)d_in[7];
    const float* bl    = (const float*)d_in[8];
    const float* gamma = (const float*)d_in[9];
    const float* beta  = (const float*)d_in[10];
    float* out = (float*)d_out;

    float *pq, *pk, *pv, *pattn, *ph;
    cudaGetSymbolAddress((void**)&pq, g_q);
    cudaGetSymbolAddress((void**)&pk, g_k);
    cudaGetSymbolAddress((void**)&pv, g_v);
    cudaGetSymbolAddress((void**)&pattn, g_attn);
    cudaGetSymbolAddress((void**)&ph, g_h);

    cudaFuncSetAttribute(attn_mma_kernel, cudaFuncAttributeMaxDynamicSharedMemorySize,
                         ATTN_SMEM);
    cudaFuncSetAttribute(gemm_mma_kernel, cudaFuncAttributeMaxDynamicSharedMemorySize,
                         GEMM_SMEM);

    // projections (tensor-core tf32)
    gemm_mma_kernel<<<dim3(MTOT / 128, 1), 256, GEMM_SMEM>>>(x, Wq, bq, pq, DA);
    gemm_mma_kernel<<<dim3(MTOT / 128, 1), 256, GEMM_SMEM>>>(x, Wk, bk, pk, DA);
    gemm_mma_kernel<<<dim3(MTOT / 128, 4), 256, GEMM_SMEM>>>(x, Wv, bv, pv, DE);

    // attention
    attn_mma_kernel<<<dim3(SEQ / 128, BATCH), 256, ATTN_SMEM>>>(pq, pk, pv, pattn);

    // h = attn @ Wl + bl (tensor-core tf32; BN is scale-invariant to the tf32
    // truncation bias so fp32 accuracy is preserved at the output)
    gemm_mma_kernel<<<dim3(MTOT / 128, 4), 256, GEMM_SMEM>>>(pattn, Wl, bl, ph, DE);

    // batchnorm + relu + residual
    bn_zero_kernel<<<1, 256>>>();
    bn_stats_kernel<<<MTOT / 128, 256>>>(ph);
    bn_finalize_kernel<<<(MTOT * DE) / 4 / 256, 256>>>(ph, x, gamma, beta, out);
}

// round 6
// speedup vs baseline: 5.0223x; 1.0204x over previous
#include <cuda_runtime.h>
#include <cuda_bf16.h>
#include <cstdint>
#include <math.h>

#define BATCH 16
#define SEQ   2048
#define DE    256
#define DA    64
#define MTOT  (BATCH*SEQ)   // 32768

// ---------------- scratch ----------------
__device__ float g_q[MTOT * DA];      // 8 MB
__device__ float g_k[MTOT * DA];      // 8 MB
__device__ float g_v[MTOT * DE];      // 32 MB
__device__ float g_attn[MTOT * DE];   // 32 MB
__device__ float g_h[MTOT * DE];      // 32 MB
__device__ float g_sum[DE];
__device__ float g_sumsq[DE];

// ================= helpers =================
__device__ __forceinline__ uint32_t smem_to_u32(const void* p) {
    uint32_t a;
    asm("{ .reg .u64 t; cvta.to.shared.u64 t, %1; cvt.u32.u64 %0, t; }" : "=r"(a) : "l"(p));
    return a;
}
__device__ __forceinline__ uint32_t tf32_bits(float x) {
    uint32_t u;
    asm("cvt.rna.tf32.f32 %0, %1;" : "=r"(u) : "f"(x));
    return u;
}
__device__ __forceinline__ void mma_tf32(float* c, const uint32_t* a,
                                         uint32_t b0, uint32_t b1) {
    asm volatile(
        "mma.sync.aligned.m16n8k8.row.col.f32.tf32.tf32.f32 "
        "{%0,%1,%2,%3}, {%4,%5,%6,%7}, {%8,%9}, {%0,%1,%2,%3};"
        : "+f"(c[0]), "+f"(c[1]), "+f"(c[2]), "+f"(c[3])
        : "r"(a[0]), "r"(a[1]), "r"(a[2]), "r"(a[3]), "r"(b0), "r"(b1));
}
__device__ __forceinline__ void cp_async16(uint32_t dst, const void* src) {
    asm volatile("cp.async.cg.shared.global [%0], [%1], 16;" :: "r"(dst), "l"(src));
}

// ---------------- mma.sync tf32 GEMM (unchanged from R5) ----------------
#define GA_F 4096
#define GW_F 2048
#define GEMM_SMEM ((2*GA_F + 2*GW_F)*4)

__global__ void __launch_bounds__(256)
gemm_mma_kernel(const float* __restrict__ A,
                const float* __restrict__ W,
                const float* __restrict__ bias,
                float* __restrict__ C, int Ncols) {
    extern __shared__ float sm[];
    float* smA = sm;
    float* smW = sm + 2 * GA_F;
    const uint32_t sbA = smem_to_u32(smA);
    const uint32_t sbW = smem_to_u32(smW);

    const int tid = threadIdx.x;
    const int lane = tid & 31, w = tid >> 5;
    const int g = lane >> 2, t = lane & 3;
    const int mw = w >> 1, nw = w & 1;
    const int bm = blockIdx.x * 128;
    const int bn = blockIdx.y * 64;

    float c[2][4][4];
    #pragma unroll
    for (int mb = 0; mb < 2; mb++)
        #pragma unroll
        for (int nb = 0; nb < 4; nb++)
            c[mb][nb][0] = c[mb][nb][1] = c[mb][nb][2] = c[mb][nb][3] = 0.f;

    auto issue2 = [&](int chunk, int stage) {
        const int k0 = chunk * 32;
        #pragma unroll
        for (int i = 0; i < 4; i++) {
            int idx = tid + i * 256;
            int m = idx >> 3, k4 = idx & 7;
            cp_async16(sbA + (uint32_t)(stage * GA_F + m * 32 + (k4 ^ (m & 7)) * 4) * 4u,
                       A + (size_t)(bm + m) * 256 + k0 + k4 * 4);
        }
        #pragma unroll
        for (int i = 0; i < 2; i++) {
            int idx = tid + i * 256;
            int kk = idx >> 4, n4 = idx & 15;
            cp_async16(sbW + (uint32_t)(stage * GW_F + kk * 64 + (n4 ^ (2 * (kk & 3))) * 4) * 4u,
                       W + (size_t)(k0 + kk) * Ncols + bn + n4 * 4);
        }
    };

    issue2(0, 0);
    asm volatile("cp.async.commit_group;" ::: "memory");

    for (int ch = 0; ch < 8; ch++) {
        if (ch + 1 < 8) {
            issue2(ch + 1, (ch + 1) & 1);
            asm volatile("cp.async.commit_group;" ::: "memory");
            asm volatile("cp.async.wait_group 1;" ::: "memory");
        } else {
            asm volatile("cp.async.wait_group 0;" ::: "memory");
        }
        __syncthreads();

        const float* cA = smA + (ch & 1) * GA_F;
        const float* cW = smW + (ch & 1) * GW_F;

        uint32_t af[4][2][4];
        #pragma unroll
        for (int ks = 0; ks < 4; ks++) {
            #pragma unroll
            for (int mb = 0; mb < 2; mb++) {
                int r0 = mw * 32 + mb * 16 + g;
                int r8 = r0 + 8;
                int kA = ks * 8 + t;
                af[ks][mb][0] = __float_as_uint(cA[r0 * 32 + (((kA) >> 2) ^ (r0 & 7)) * 4 + (kA & 3)]);
                af[ks][mb][1] = __float_as_uint(cA[r8 * 32 + (((kA) >> 2) ^ (r8 & 7)) * 4 + (kA & 3)]);
                int kB = kA + 4;
                af[ks][mb][2] = __float_as_uint(cA[r0 * 32 + (((kB) >> 2) ^ (r0 & 7)) * 4 + (kB & 3)]);
                af[ks][mb][3] = __float_as_uint(cA[r8 * 32 + (((kB) >> 2) ^ (r8 & 7)) * 4 + (kB & 3)]);
            }
        }
        uint32_t bf[4][4][2];
        #pragma unroll
        for (int ks = 0; ks < 4; ks++) {
            #pragma unroll
            for (int nb = 0; nb < 4; nb++) {
                int n = nw * 32 + nb * 8 + g;
                int k1 = ks * 8 + t;
                int k2 = k1 + 4;
                bf[ks][nb][0] = __float_as_uint(cW[k1 * 64 + ((n >> 2) ^ (2 * (k1 & 3))) * 4 + (n & 3)]);
                bf[ks][nb][1] = __float_as_uint(cW[k2 * 64 + ((n >> 2) ^ (2 * (k2 & 3))) * 4 + (n & 3)]);
            }
        }
        #pragma unroll
        for (int ks = 0; ks < 4; ks++)
            #pragma unroll
            for (int mb = 0; mb < 2; mb++)
                #pragma unroll
                for (int nb = 0; nb < 4; nb++)
                    mma_tf32(c[mb][nb], af[ks][mb], bf[ks][nb][0], bf[ks][nb][1]);
        __syncthreads();
    }

    #pragma unroll
    for (int nb = 0; nb < 4; nb++) {
        int col = bn + nw * 32 + nb * 8 + 2 * t;
        float b0 = bias[col], b1 = bias[col + 1];
        #pragma unroll
        for (int mb = 0; mb < 2; mb++) {
            int row = bm + mw * 32 + mb * 16 + g;
            float2 v01 = make_float2(c[mb][nb][0] + b0, c[mb][nb][1] + b1);
            float2 v23 = make_float2(c[mb][nb][2] + b0, c[mb][nb][3] + b1);
            *(float2*)&C[(size_t)row * Ncols + col] = v01;
            *(float2*)&C[(size_t)(row + 8) * Ncols + col] = v23;
        }
    }
}

// ---------------- attention: B-fragment-reuse layout ----------------
// CTA = 128 queries, 8 warps, 64-key tiles, double-buffered K/V.
// S phase:  warp = (q-group w>>1 of 32q) x (key-half w&1 of 32 keys), M=32,N=32.
// PV phase: warp = (q-half w>>2 of 64q) x (d-group w&3 of 64d),      M=64,N=64.
// P (exp(S), tf32) goes through smem between the phases.
#define KSTR 68
#define VSTR 264
#define K_F  (64*KSTR)               // 4352 floats
#define V_F  (64*VSTR)               // 16896 floats
#define STG_F (K_F + V_F)            // 21248 floats
#define PSTR 68
#define P_F  (128*PSTR)              // 8704 floats
#define L_F  256
#define ATTN_SMEM ((2*STG_F + P_F + L_F)*4)   // 205824 bytes

__global__ void __launch_bounds__(256, 1)
attn_mma_kernel(const float* __restrict__ q,
                const float* __restrict__ k,
                const float* __restrict__ v,
                float* __restrict__ out) {
    extern __shared__ float sm[];
    float* smP = sm + 2 * STG_F;
    float* smL = smP + P_F;
    const uint32_t sbase = smem_to_u32(sm);
    const int tid = threadIdx.x;
    const int lane = tid & 31, w = tid >> 5;
    const int g = lane >> 2, t = lane & 3;
    const int b = blockIdx.y;
    const int q0 = blockIdx.x * 128;

    const int qg = w >> 1, kh = w & 1;   // S-phase mapping
    const int qh = w >> 2, dg = w & 3;   // PV-phase mapping

    const float* kb = k + (size_t)b * SEQ * DA;
    const float* vb = v + (size_t)b * SEQ * DE;

    // Q A-fragments: rows q0 + qg*32 + m*16 + g(+8), cols ks*8 + t(+4)
    uint32_t qa[2][8][4];
    {
        const float* qbase = q + (size_t)(b * SEQ + q0 + qg * 32) * DA;
        #pragma unroll
        for (int m = 0; m < 2; m++) {
            const float* r0 = qbase + (size_t)(m * 16 + g) * DA;
            const float* r8 = r0 + 8 * DA;
            #pragma unroll
            for (int ks = 0; ks < 8; ks++) {
                qa[m][ks][0] = __float_as_uint(r0[ks * 8 + t]);
                qa[m][ks][1] = __float_as_uint(r8[ks * 8 + t]);
                qa[m][ks][2] = __float_as_uint(r0[ks * 8 + t + 4]);
                qa[m][ks][3] = __float_as_uint(r8[ks * 8 + t + 4]);
            }
        }
    }

    float o[4][8][4];
    #pragma unroll
    for (int m = 0; m < 4; m++)
        #pragma unroll
        for (int nb = 0; nb < 8; nb++)
            o[m][nb][0] = o[m][nb][1] = o[m][nb][2] = o[m][nb][3] = 0.f;
    float rs[2][2] = {{0.f, 0.f}, {0.f, 0.f}};

    auto issue = [&](int tile, int stage) {
        const uint32_t kd = sbase + (uint32_t)(stage * STG_F) * 4u;
        const uint32_t vd = kd + (uint32_t)K_F * 4u;
        const float* ksrc = kb + (size_t)tile * 64 * DA;
        const float* vsrc = vb + (size_t)tile * 64 * DE;
        #pragma unroll
        for (int i = 0; i < 4; i++) {            // K: 1024 float4
            int idx = tid + i * 256;
            int r = idx >> 4, c4 = idx & 15;
            cp_async16(kd + (uint32_t)(r * KSTR + c4 * 4) * 4u, ksrc + r * 64 + c4 * 4);
        }
        #pragma unroll
        for (int i = 0; i < 16; i++) {           // V: 4096 float4
            int idx = tid + i * 256;
            int r = idx >> 6, c4 = idx & 63;
            cp_async16(vd + (uint32_t)(r * VSTR + c4 * 4) * 4u, vsrc + r * 256 + c4 * 4);
        }
    };

    issue(0, 0);
    asm volatile("cp.async.commit_group;" ::: "memory");

    for (int tile = 0; tile < SEQ / 64; tile++) {
        if (tile + 1 < SEQ / 64) {
            issue(tile + 1, (tile + 1) & 1);
            asm volatile("cp.async.commit_group;" ::: "memory");
            asm volatile("cp.async.wait_group 1;" ::: "memory");
        } else {
            asm volatile("cp.async.wait_group 0;" ::: "memory");
        }
        __syncthreads();

        const float* sK = sm + (tile & 1) * STG_F;
        const float* sV = sK + K_F;

        // ---- S: 32 queries x 32 keys per warp (B fragments reused x2) ----
        float c[2][4][4];
        #pragma unroll
        for (int m = 0; m < 2; m++)
            #pragma unroll
            for (int nb = 0; nb < 4; nb++)
                c[m][nb][0] = c[m][nb][1] = c[m][nb][2] = c[m][nb][3] = 0.f;
        #pragma unroll
        for (int ks = 0; ks < 8; ks++) {
            #pragma unroll
            for (int nb = 0; nb < 4; nb++) {
                const float* kr = sK + (kh * 32 + nb * 8 + g) * KSTR + ks * 8 + t;
                uint32_t b0 = __float_as_uint(kr[0]);
                uint32_t b1 = __float_as_uint(kr[4]);
                mma_tf32(c[0][nb], qa[0][ks], b0, b1);
                mma_tf32(c[1][nb], qa[1][ks], b0, b1);
            }
        }

        // ---- P = exp(S/64) -> smem (tf32), accumulate row sums ----
        #pragma unroll
        for (int m = 0; m < 2; m++) {
            float* pr = smP + (qg * 32 + m * 16 + g) * PSTR + kh * 32;
            float* pr8 = pr + 8 * PSTR;
            #pragma unroll
            for (int nb = 0; nb < 4; nb++) {
                float e0 = __expf(c[m][nb][0] * 0.015625f);
                float e1 = __expf(c[m][nb][1] * 0.015625f);
                float e2 = __expf(c[m][nb][2] * 0.015625f);
                float e3 = __expf(c[m][nb][3] * 0.015625f);
                rs[m][0] += e0 + e1;
                rs[m][1] += e2 + e3;
                *(float2*)&pr[nb * 8 + 2 * t] =
                    make_float2(__uint_as_float(tf32_bits(e0)), __uint_as_float(tf32_bits(e1)));
                *(float2*)&pr8[nb * 8 + 2 * t] =
                    make_float2(__uint_as_float(tf32_bits(e2)), __uint_as_float(tf32_bits(e3)));
            }
        }
        __syncthreads();

        // ---- O += P @ V : 64 queries x 64 d per warp (B fragments reused x4) ----
        #pragma unroll
        for (int ks = 0; ks < 8; ks++) {
            uint32_t pf[4][4];
            #pragma unroll
            for (int m = 0; m < 4; m++) {
                const float* p0 = smP + (qh * 64 + m * 16 + g) * PSTR + ks * 8 + t;
                const float* p8 = p0 + 8 * PSTR;
                pf[m][0] = __float_as_uint(p0[0]);
                pf[m][1] = __float_as_uint(p8[0]);
                pf[m][2] = __float_as_uint(p0[4]);
                pf[m][3] = __float_as_uint(p8[4]);
            }
            #pragma unroll
            for (int nb = 0; nb < 8; nb++) {
                const float* vr = sV + (ks * 8 + t) * VSTR + dg * 64 + nb * 8 + g;
                uint32_t b0 = __float_as_uint(vr[0]);
                uint32_t b1 = __float_as_uint(vr[4 * VSTR]);
                #pragma unroll
                for (int m = 0; m < 4; m++)
                    mma_tf32(o[m][nb], pf[m], b0, b1);
            }
        }
        __syncthreads();
    }

    // ---- row-sum reduction: over t-lanes, then over the 2 key-half warps ----
    #pragma unroll
    for (int m = 0; m < 2; m++)
        #pragma unroll
        for (int r = 0; r < 2; r++) {
            rs[m][r] += __shfl_xor_sync(0xffffffff, rs[m][r], 1);
            rs[m][r] += __shfl_xor_sync(0xffffffff, rs[m][r], 2);
        }
    if (t == 0) {
        #pragma unroll
        for (int m = 0; m < 2; m++)
            #pragma unroll
            for (int r = 0; r < 2; r++)
                smL[kh * 128 + qg * 32 + m * 16 + r * 8 + g] = rs[m][r];
    }
    __syncthreads();

    // ---- epilogue: scale by 1/lsum, store ----
    #pragma unroll
    for (int m = 0; m < 4; m++) {
        int qrow = qh * 64 + m * 16 + g;
        float inv0 = 1.f / (smL[qrow] + smL[128 + qrow]);
        float inv8 = 1.f / (smL[qrow + 8] + smL[128 + qrow + 8]);
        float* out0 = out + (size_t)(b * SEQ + q0 + qrow) * DE + dg * 64;
        float* out8 = out0 + 8 * DE;
        #pragma unroll
        for (int nb = 0; nb < 8; nb++) {
            *(float2*)&out0[nb * 8 + 2 * t] =
                make_float2(o[m][nb][0] * inv0, o[m][nb][1] * inv0);
            *(float2*)&out8[nb * 8 + 2 * t] =
                make_float2(o[m][nb][2] * inv8, o[m][nb][3] * inv8);
        }
    }
}

// ---------------- BatchNorm pieces ----------------
__global__ void bn_zero_kernel() {
    int tidx = threadIdx.x;
    g_sum[tidx] = 0.f;
    g_sumsq[tidx] = 0.f;
}

__global__ void bn_stats_kernel(const float* __restrict__ h) {
    const int c = threadIdx.x;
    const int r0 = blockIdx.x * 128;
    float s = 0.f, s2 = 0.f;
    #pragma unroll 4
    for (int r = 0; r < 128; r++) {
        float x = h[(size_t)(r0 + r) * DE + c];
        s += x;
        s2 += x * x;
    }
    atomicAdd(&g_sum[c], s);
    atomicAdd(&g_sumsq[c], s2);
}

__global__ void bn_finalize_kernel(const float* __restrict__ h,
                                   const float* __restrict__ x,
                                   const float* __restrict__ gamma,
                                   const float* __restrict__ beta,
                                   float* __restrict__ y) {
    const int idx = blockIdx.x * 256 + threadIdx.x;
    const int c0 = (idx * 4) & 255;
    const float invM = 1.f / (float)MTOT;
    float4 hv = ((const float4*)h)[idx];
    float4 xv = ((const float4*)x)[idx];
    float r[4];
    float hvv[4] = {hv.x, hv.y, hv.z, hv.w};
    float xvv[4] = {xv.x, xv.y, xv.z, xv.w};
    #pragma unroll
    for (int u = 0; u < 4; u++) {
        int c = c0 + u;
        float mean = g_sum[c] * invM;
        float var = g_sumsq[c] * invM - mean * mean;
        float rsv = rsqrtf(var + 1e-5f);
        float val = (hvv[u] - mean) * rsv * gamma[c] + beta[c];
        r[u] = fmaxf(val, 0.f) + xvv[u];
    }
    float4 ov = {r[0], r[1], r[2], r[3]};
    ((float4*)y)[idx] = ov;
}

// ---------------- launch ----------------
extern "C" void kernel_launch(void* const* d_in, const int* in_sizes, int n_in,
                              void* d_out, int out_size) {
    const float* x     = (const float*)d_in[0];
    const float* Wq    = (const float*)d_in[1];
    const float* bq    = (const float*)d_in[2];
    const float* Wk    = (const float*)d_in[3];
    const float* bk    = (const float*)d_in[4];
    const float* Wv    = (const float*)d_in[5];
    const float* bv    = (const float*)d_in[6];
    const float* Wl    = (const float*)d_in[7];
    const float* bl    = (const float*)d_in[8];
    const float* gamma = (const float*)d_in[9];
    const float* beta  = (const float*)d_in[10];
    float* out = (float*)d_out;

    float *pq, *pk, *pv, *pattn, *ph;
    cudaGetSymbolAddress((void**)&pq, g_q);
    cudaGetSymbolAddress((void**)&pk, g_k);
    cudaGetSymbolAddress((void**)&pv, g_v);
    cudaGetSymbolAddress((void**)&pattn, g_attn);
    cudaGetSymbolAddress((void**)&ph, g_h);

    cudaFuncSetAttribute(attn_mma_kernel, cudaFuncAttributeMaxDynamicSharedMemorySize,
                         ATTN_SMEM);
    cudaFuncSetAttribute(gemm_mma_kernel, cudaFuncAttributeMaxDynamicSharedMemorySize,
                         GEMM_SMEM);

    // projections (tensor-core tf32)
    gemm_mma_kernel<<<dim3(MTOT / 128, 1), 256, GEMM_SMEM>>>(x, Wq, bq, pq, DA);
    gemm_mma_kernel<<<dim3(MTOT / 128, 1), 256, GEMM_SMEM>>>(x, Wk, bk, pk, DA);
    gemm_mma_kernel<<<dim3(MTOT / 128, 4), 256, GEMM_SMEM>>>(x, Wv, bv, pv, DE);

    // attention
    attn_mma_kernel<<<dim3(SEQ / 128, BATCH), 256, ATTN_SMEM>>>(pq, pk, pv, pattn);

    // h = attn @ Wl + bl
    gemm_mma_kernel<<<dim3(MTOT / 128, 4), 256, GEMM_SMEM>>>(pattn, Wl, bl, ph, DE);

    // batchnorm + relu + residual
    bn_zero_kernel<<<1, 256>>>();
    bn_stats_kernel<<<MTOT / 128, 256>>>(ph);
    bn_finalize_kernel<<<(MTOT * DE) / 4 / 256, 256>>>(ph, x, gamma, beta, out);
}

// round 7
// speedup vs baseline: 7.6886x; 1.5309x over previous
#include <cuda_runtime.h>
#include <cuda_bf16.h>
#include <cuda_fp16.h>
#include <cstdint>
#include <math.h>

#define BATCH 16
#define SEQ   2048
#define DE    256
#define DA    64
#define MTOT  (BATCH*SEQ)   // 32768

// ---------------- scratch ----------------
__device__ __half g_qh[MTOT * DA];     // 4 MB, [tok][d] fp16
__device__ __half g_kh[MTOT * DA];     // 4 MB, [tok][d] fp16
__device__ __half g_vh[MTOT * DE];     // 16 MB, key-interleaved [tok/2][d][tok&1]
__device__ float  g_attn[MTOT * DE];   // 32 MB
__device__ float  g_h[MTOT * DE];      // 32 MB
__device__ float  g_sum[DE];
__device__ float  g_sumsq[DE];

// ================= helpers =================
__device__ __forceinline__ uint32_t smem_to_u32(const void* p) {
    uint32_t a;
    asm("{ .reg .u64 t; cvta.to.shared.u64 t, %1; cvt.u32.u64 %0, t; }" : "=r"(a) : "l"(p));
    return a;
}
__device__ __forceinline__ void mma_tf32(float* c, const uint32_t* a,
                                         uint32_t b0, uint32_t b1) {
    asm volatile(
        "mma.sync.aligned.m16n8k8.row.col.f32.tf32.tf32.f32 "
        "{%0,%1,%2,%3}, {%4,%5,%6,%7}, {%8,%9}, {%0,%1,%2,%3};"
        : "+f"(c[0]), "+f"(c[1]), "+f"(c[2]), "+f"(c[3])
        : "r"(a[0]), "r"(a[1]), "r"(a[2]), "r"(a[3]), "r"(b0), "r"(b1));
}
__device__ __forceinline__ void mma_f16(float* c, const uint32_t* a,
                                        uint32_t b0, uint32_t b1) {
    asm volatile(
        "mma.sync.aligned.m16n8k16.row.col.f32.f16.f16.f32 "
        "{%0,%1,%2,%3}, {%4,%5,%6,%7}, {%8,%9}, {%0,%1,%2,%3};"
        : "+f"(c[0]), "+f"(c[1]), "+f"(c[2]), "+f"(c[3])
        : "r"(a[0]), "r"(a[1]), "r"(a[2]), "r"(a[3]), "r"(b0), "r"(b1));
}
__device__ __forceinline__ void cp_async16(uint32_t dst, const void* src) {
    asm volatile("cp.async.cg.shared.global [%0], [%1], 16;" :: "r"(dst), "l"(src));
}

// ---------------- mma.sync tf32 GEMM with fp16 output modes ----------------
// mode 0: fp32 [row][col]   mode 1: fp16 [row][col]   mode 2: fp16 interleaved V
#define GA_F 4096
#define GW_F 2048
#define GEMM_SMEM ((2*GA_F + 2*GW_F)*4)

__global__ void __launch_bounds__(256)
gemm_mma_kernel(const float* __restrict__ A,
                const float* __restrict__ W,
                const float* __restrict__ bias,
                void* __restrict__ Cout, int Ncols, int mode) {
    extern __shared__ float sm[];
    float* smA = sm;
    float* smW = sm + 2 * GA_F;
    const uint32_t sbA = smem_to_u32(smA);
    const uint32_t sbW = smem_to_u32(smW);

    const int tid = threadIdx.x;
    const int lane = tid & 31, w = tid >> 5;
    const int g = lane >> 2, t = lane & 3;
    const int mw = w >> 1, nw = w & 1;
    const int bm = blockIdx.x * 128;
    const int bn = blockIdx.y * 64;

    float c[2][4][4];
    #pragma unroll
    for (int mb = 0; mb < 2; mb++)
        #pragma unroll
        for (int nb = 0; nb < 4; nb++)
            c[mb][nb][0] = c[mb][nb][1] = c[mb][nb][2] = c[mb][nb][3] = 0.f;

    auto issue2 = [&](int chunk, int stage) {
        const int k0 = chunk * 32;
        #pragma unroll
        for (int i = 0; i < 4; i++) {
            int idx = tid + i * 256;
            int m = idx >> 3, k4 = idx & 7;
            cp_async16(sbA + (uint32_t)(stage * GA_F + m * 32 + (k4 ^ (m & 7)) * 4) * 4u,
                       A + (size_t)(bm + m) * 256 + k0 + k4 * 4);
        }
        #pragma unroll
        for (int i = 0; i < 2; i++) {
            int idx = tid + i * 256;
            int kk = idx >> 4, n4 = idx & 15;
            cp_async16(sbW + (uint32_t)(stage * GW_F + kk * 64 + (n4 ^ (2 * (kk & 3))) * 4) * 4u,
                       W + (size_t)(k0 + kk) * Ncols + bn + n4 * 4);
        }
    };

    issue2(0, 0);
    asm volatile("cp.async.commit_group;" ::: "memory");

    for (int ch = 0; ch < 8; ch++) {
        if (ch + 1 < 8) {
            issue2(ch + 1, (ch + 1) & 1);
            asm volatile("cp.async.commit_group;" ::: "memory");
            asm volatile("cp.async.wait_group 1;" ::: "memory");
        } else {
            asm volatile("cp.async.wait_group 0;" ::: "memory");
        }
        __syncthreads();

        const float* cA = smA + (ch & 1) * GA_F;
        const float* cW = smW + (ch & 1) * GW_F;

        uint32_t af[4][2][4];
        #pragma unroll
        for (int ks = 0; ks < 4; ks++) {
            #pragma unroll
            for (int mb = 0; mb < 2; mb++) {
                int r0 = mw * 32 + mb * 16 + g;
                int r8 = r0 + 8;
                int kA = ks * 8 + t;
                af[ks][mb][0] = __float_as_uint(cA[r0 * 32 + (((kA) >> 2) ^ (r0 & 7)) * 4 + (kA & 3)]);
                af[ks][mb][1] = __float_as_uint(cA[r8 * 32 + (((kA) >> 2) ^ (r8 & 7)) * 4 + (kA & 3)]);
                int kB = kA + 4;
                af[ks][mb][2] = __float_as_uint(cA[r0 * 32 + (((kB) >> 2) ^ (r0 & 7)) * 4 + (kB & 3)]);
                af[ks][mb][3] = __float_as_uint(cA[r8 * 32 + (((kB) >> 2) ^ (r8 & 7)) * 4 + (kB & 3)]);
            }
        }
        uint32_t bf[4][4][2];
        #pragma unroll
        for (int ks = 0; ks < 4; ks++) {
            #pragma unroll
            for (int nb = 0; nb < 4; nb++) {
                int n = nw * 32 + nb * 8 + g;
                int k1 = ks * 8 + t;
                int k2 = k1 + 4;
                bf[ks][nb][0] = __float_as_uint(cW[k1 * 64 + ((n >> 2) ^ (2 * (k1 & 3))) * 4 + (n & 3)]);
                bf[ks][nb][1] = __float_as_uint(cW[k2 * 64 + ((n >> 2) ^ (2 * (k2 & 3))) * 4 + (n & 3)]);
            }
        }
        #pragma unroll
        for (int ks = 0; ks < 4; ks++)
            #pragma unroll
            for (int mb = 0; mb < 2; mb++)
                #pragma unroll
                for (int nb = 0; nb < 4; nb++)
                    mma_tf32(c[mb][nb], af[ks][mb], bf[ks][nb][0], bf[ks][nb][1]);
        __syncthreads();
    }

    #pragma unroll
    for (int nb = 0; nb < 4; nb++) {
        int col = bn + nw * 32 + nb * 8 + 2 * t;
        float b0 = bias[col], b1 = bias[col + 1];
        #pragma unroll
        for (int mb = 0; mb < 2; mb++) {
            int row = bm + mw * 32 + mb * 16 + g;
            float v00 = c[mb][nb][0] + b0, v01 = c[mb][nb][1] + b1;
            float v10 = c[mb][nb][2] + b0, v11 = c[mb][nb][3] + b1;
            if (mode == 0) {
                float* C = (float*)Cout;
                *(float2*)&C[(size_t)row * Ncols + col] = make_float2(v00, v01);
                *(float2*)&C[(size_t)(row + 8) * Ncols + col] = make_float2(v10, v11);
            } else if (mode == 1) {
                __half2* C2 = (__half2*)Cout;
                C2[((size_t)row * Ncols + col) >> 1] = __floats2half2_rn(v00, v01);
                C2[((size_t)(row + 8) * Ncols + col) >> 1] = __floats2half2_rn(v10, v11);
            } else {
                __half* Ch = (__half*)Cout;
                int r2 = row + 8;
                Ch[(size_t)(row >> 1) * 512 + col * 2 + (row & 1)]       = __float2half_rn(v00);
                Ch[(size_t)(row >> 1) * 512 + (col + 1) * 2 + (row & 1)] = __float2half_rn(v01);
                Ch[(size_t)(r2 >> 1) * 512 + col * 2 + (r2 & 1)]         = __float2half_rn(v10);
                Ch[(size_t)(r2 >> 1) * 512 + (col + 1) * 2 + (r2 & 1)]   = __float2half_rn(v11);
            }
        }
    }
}

// ---------------- fp16 mma.sync flash attention ----------------
// CTA = 128 queries, 8 warps, 64-key tiles, double-buffered K/V fp16.
// S phase:  warp = (q-group w>>1) x (key-half w&1): M=32, N=32, m16n8k16.
// PV phase: warp = (q-half w>>2) x (d-group w&3):  M=64, N=64.
// K smem: [64 keys][72 halfs]; V smem: [32 keypairs][264 words] (interleaved);
// P smem: [128 q][72 halfs] fp16.
#define KSTRH 72
#define KFH   (64*KSTRH)            // 4608 halfs
#define VSTRW 264
#define VFW   (32*VSTRW)            // 8448 words = 16896 halfs
#define STGH  (KFH + 2*VFW)         // 21504 halfs per stage
#define PSTRH 72
#define PFH   (128*PSTRH)           // 9216 halfs
#define ATTN_SMEM (2*STGH*2 + PFH*2 + 256*4)   // 105472 bytes

__global__ void __launch_bounds__(256, 1)
attn_mma_kernel(const __half* __restrict__ q,
                const __half* __restrict__ k,
                const __half* __restrict__ v,
                float* __restrict__ out) {
    extern __shared__ __half smh[];
    __half* smP = smh + 2 * STGH;
    float* smL = (float*)(smh + 2 * STGH + PFH);
    const uint32_t sbase = smem_to_u32(smh);
    const int tid = threadIdx.x;
    const int lane = tid & 31, w = tid >> 5;
    const int g = lane >> 2, t = lane & 3;
    const int b = blockIdx.y;
    const int q0 = blockIdx.x * 128;

    const int qg = w >> 1, kh = w & 1;   // S-phase mapping
    const int qh = w >> 2, dg = w & 3;   // PV-phase mapping

    const __half* kb = k + (size_t)b * SEQ * DA;
    const __half* vb = v + (size_t)b * SEQ * DE;   // interleaved within batch

    // Q A-fragments (m16n8k16): 2 q-subtiles x 4 k-steps x 4 regs
    uint32_t qa[2][4][4];
    {
        const __half* qbase = q + (size_t)(b * SEQ + q0 + qg * 32) * DA;
        #pragma unroll
        for (int m = 0; m < 2; m++) {
            const __half* r0 = qbase + (size_t)(m * 16 + g) * DA;
            const __half* r8 = r0 + 8 * DA;
            #pragma unroll
            for (int ks = 0; ks < 4; ks++) {
                qa[m][ks][0] = *(const uint32_t*)(r0 + ks * 16 + 2 * t);
                qa[m][ks][1] = *(const uint32_t*)(r8 + ks * 16 + 2 * t);
                qa[m][ks][2] = *(const uint32_t*)(r0 + ks * 16 + 2 * t + 8);
                qa[m][ks][3] = *(const uint32_t*)(r8 + ks * 16 + 2 * t + 8);
            }
        }
    }

    float o[4][8][4];
    #pragma unroll
    for (int m = 0; m < 4; m++)
        #pragma unroll
        for (int nb = 0; nb < 8; nb++)
            o[m][nb][0] = o[m][nb][1] = o[m][nb][2] = o[m][nb][3] = 0.f;
    float rs[2][2] = {{0.f, 0.f}, {0.f, 0.f}};

    auto issue = [&](int tile, int stage) {
        const uint32_t kd = sbase + (uint32_t)(stage * STGH) * 2u;
        const uint32_t vd = kd + (uint32_t)KFH * 2u;
        const __half* ksrc = kb + (size_t)tile * 64 * DA;
        const __half* vsrc = vb + (size_t)tile * 32 * 512;
        #pragma unroll
        for (int i = 0; i < 2; i++) {            // K: 512 x 16B
            int idx = tid + i * 256;
            int r = idx >> 3, c16 = idx & 7;
            cp_async16(kd + (uint32_t)(r * KSTRH * 2 + c16 * 16), ksrc + r * 64 + c16 * 8);
        }
        #pragma unroll
        for (int i = 0; i < 8; i++) {            // V: 2048 x 16B
            int idx = tid + i * 256;
            int r = idx >> 6, ch = idx & 63;
            cp_async16(vd + (uint32_t)(r * VSTRW * 4 + ch * 16), vsrc + (size_t)r * 512 + ch * 8);
        }
    };

    issue(0, 0);
    asm volatile("cp.async.commit_group;" ::: "memory");

    for (int tile = 0; tile < SEQ / 64; tile++) {
        if (tile + 1 < SEQ / 64) {
            issue(tile + 1, (tile + 1) & 1);
            asm volatile("cp.async.commit_group;" ::: "memory");
            asm volatile("cp.async.wait_group 1;" ::: "memory");
        } else {
            asm volatile("cp.async.wait_group 0;" ::: "memory");
        }
        __syncthreads();

        const __half* sK = smh + (tile & 1) * STGH;
        const uint32_t* sVw = (const uint32_t*)(sK + KFH);

        // ---- S: 32 q x 32 keys per warp ----
        float c[2][4][4];
        #pragma unroll
        for (int m = 0; m < 2; m++)
            #pragma unroll
            for (int nb = 0; nb < 4; nb++)
                c[m][nb][0] = c[m][nb][1] = c[m][nb][2] = c[m][nb][3] = 0.f;
        #pragma unroll
        for (int ks = 0; ks < 4; ks++) {
            #pragma unroll
            for (int nb = 0; nb < 4; nb++) {
                const __half* kr = sK + (kh * 32 + nb * 8 + g) * KSTRH + ks * 16 + 2 * t;
                uint32_t b0 = *(const uint32_t*)kr;
                uint32_t b1 = *(const uint32_t*)(kr + 8);
                mma_f16(c[0][nb], qa[0][ks], b0, b1);
                mma_f16(c[1][nb], qa[1][ks], b0, b1);
            }
        }

        // ---- P = exp(S/64) -> smem fp16, accumulate row sums ----
        #pragma unroll
        for (int m = 0; m < 2; m++) {
            __half* pr = smP + (qg * 32 + m * 16 + g) * PSTRH + kh * 32;
            __half* pr8 = pr + 8 * PSTRH;
            #pragma unroll
            for (int nb = 0; nb < 4; nb++) {
                float e0 = __expf(c[m][nb][0] * 0.015625f);
                float e1 = __expf(c[m][nb][1] * 0.015625f);
                float e2 = __expf(c[m][nb][2] * 0.015625f);
                float e3 = __expf(c[m][nb][3] * 0.015625f);
                rs[m][0] += e0 + e1;
                rs[m][1] += e2 + e3;
                *(__half2*)(pr + nb * 8 + 2 * t) = __floats2half2_rn(e0, e1);
                *(__half2*)(pr8 + nb * 8 + 2 * t) = __floats2half2_rn(e2, e3);
            }
        }
        __syncthreads();

        // ---- O += P @ V : 64 q x 64 d per warp ----
        #pragma unroll
        for (int ks = 0; ks < 4; ks++) {
            uint32_t pf[4][4];
            #pragma unroll
            for (int m = 0; m < 4; m++) {
                const __half* p0 = smP + (qh * 64 + m * 16 + g) * PSTRH + ks * 16 + 2 * t;
                pf[m][0] = *(const uint32_t*)p0;
                pf[m][1] = *(const uint32_t*)(p0 + 8 * PSTRH);
                pf[m][2] = *(const uint32_t*)(p0 + 8);
                pf[m][3] = *(const uint32_t*)(p0 + 8 * PSTRH + 8);
            }
            #pragma unroll
            for (int nb = 0; nb < 8; nb++) {
                const uint32_t* vw = sVw + (ks * 8 + t) * VSTRW + dg * 64 + nb * 8 + g;
                uint32_t b0 = vw[0];
                uint32_t b1 = vw[4 * VSTRW];
                #pragma unroll
                for (int m = 0; m < 4; m++)
                    mma_f16(o[m][nb], pf[m], b0, b1);
            }
        }
        __syncthreads();
    }

    // ---- row-sum reduction across quad lanes + 2 key-half warps ----
    #pragma unroll
    for (int m = 0; m < 2; m++)
        #pragma unroll
        for (int r = 0; r < 2; r++) {
            rs[m][r] += __shfl_xor_sync(0xffffffff, rs[m][r], 1);
            rs[m][r] += __shfl_xor_sync(0xffffffff, rs[m][r], 2);
        }
    if (t == 0) {
        #pragma unroll
        for (int m = 0; m < 2; m++)
            #pragma unroll
            for (int r = 0; r < 2; r++)
                smL[kh * 128 + qg * 32 + m * 16 + r * 8 + g] = rs[m][r];
    }
    __syncthreads();

    // ---- epilogue ----
    #pragma unroll
    for (int m = 0; m < 4; m++) {
        int qrow = qh * 64 + m * 16 + g;
        float inv0 = 1.f / (smL[qrow] + smL[128 + qrow]);
        float inv8 = 1.f / (smL[qrow + 8] + smL[128 + qrow + 8]);
        float* out0 = out + (size_t)(b * SEQ + q0 + qrow) * DE + dg * 64;
        float* out8 = out0 + 8 * DE;
        #pragma unroll
        for (int nb = 0; nb < 8; nb++) {
            *(float2*)&out0[nb * 8 + 2 * t] =
                make_float2(o[m][nb][0] * inv0, o[m][nb][1] * inv0);
            *(float2*)&out8[nb * 8 + 2 * t] =
                make_float2(o[m][nb][2] * inv8, o[m][nb][3] * inv8);
        }
    }
}

// ---------------- BatchNorm pieces ----------------
__global__ void bn_zero_kernel() {
    int tidx = threadIdx.x;
    g_sum[tidx] = 0.f;
    g_sumsq[tidx] = 0.f;
}

__global__ void bn_stats_kernel(const float* __restrict__ h) {
    const int c = threadIdx.x;
    const int r0 = blockIdx.x * 128;
    float s = 0.f, s2 = 0.f;
    #pragma unroll 4
    for (int r = 0; r < 128; r++) {
        float x = h[(size_t)(r0 + r) * DE + c];
        s += x;
        s2 += x * x;
    }
    atomicAdd(&g_sum[c], s);
    atomicAdd(&g_sumsq[c], s2);
}

__global__ void bn_finalize_kernel(const float* __restrict__ h,
                                   const float* __restrict__ x,
                                   const float* __restrict__ gamma,
                                   const float* __restrict__ beta,
                                   float* __restrict__ y) {
    const int idx = blockIdx.x * 256 + threadIdx.x;
    const int c0 = (idx * 4) & 255;
    const float invM = 1.f / (float)MTOT;
    float4 hv = ((const float4*)h)[idx];
    float4 xv = ((const float4*)x)[idx];
    float r[4];
    float hvv[4] = {hv.x, hv.y, hv.z, hv.w};
    float xvv[4] = {xv.x, xv.y, xv.z, xv.w};
    #pragma unroll
    for (int u = 0; u < 4; u++) {
        int c = c0 + u;
        float mean = g_sum[c] * invM;
        float var = g_sumsq[c] * invM - mean * mean;
        float rsv = rsqrtf(var + 1e-5f);
        float val = (hvv[u] - mean) * rsv * gamma[c] + beta[c];
        r[u] = fmaxf(val, 0.f) + xvv[u];
    }
    float4 ov = {r[0], r[1], r[2], r[3]};
    ((float4*)y)[idx] = ov;
}

// ---------------- launch ----------------
extern "C" void kernel_launch(void* const* d_in, const int* in_sizes, int n_in,
                              void* d_out, int out_size) {
    const float* x     = (const float*)d_in[0];
    const float* Wq    = (const float*)d_in[1];
    const float* bq    = (const float*)d_in[2];
    const float* Wk    = (const float*)d_in[3];
    const float* bk    = (const float*)d_in[4];
    const float* Wv    = (const float*)d_in[5];
    const float* bv    = (const float*)d_in[6];
    const float* Wl    = (const float*)d_in[7];
    const float* bl    = (const float*)d_in[8];
    const float* gamma = (const float*)d_in[9];
    const float* beta  = (const float*)d_in[10];
    float* out = (float*)d_out;

    __half *pqh, *pkh, *pvh;
    float *pattn, *ph;
    cudaGetSymbolAddress((void**)&pqh, g_qh);
    cudaGetSymbolAddress((void**)&pkh, g_kh);
    cudaGetSymbolAddress((void**)&pvh, g_vh);
    cudaGetSymbolAddress((void**)&pattn, g_attn);
    cudaGetSymbolAddress((void**)&ph, g_h);

    cudaFuncSetAttribute(attn_mma_kernel, cudaFuncAttributeMaxDynamicSharedMemorySize,
                         ATTN_SMEM);
    cudaFuncSetAttribute(gemm_mma_kernel, cudaFuncAttributeMaxDynamicSharedMemorySize,
                         GEMM_SMEM);

    // projections (tf32 compute, fp16 outputs)
    gemm_mma_kernel<<<dim3(MTOT / 128, 1), 256, GEMM_SMEM>>>(x, Wq, bq, pqh, DA, 1);
    gemm_mma_kernel<<<dim3(MTOT / 128, 1), 256, GEMM_SMEM>>>(x, Wk, bk, pkh, DA, 1);
    gemm_mma_kernel<<<dim3(MTOT / 128, 4), 256, GEMM_SMEM>>>(x, Wv, bv, pvh, DE, 2);

    // attention (fp16 m16n8k16)
    attn_mma_kernel<<<dim3(SEQ / 128, BATCH), 256, ATTN_SMEM>>>(pqh, pkh, pvh, pattn);

    // h = attn @ Wl + bl (tf32, fp32 out)
    gemm_mma_kernel<<<dim3(MTOT / 128, 4), 256, GEMM_SMEM>>>(pattn, Wl, bl, ph, DE, 0);

    // batchnorm + relu + residual
    bn_zero_kernel<<<1, 256>>>();
    bn_stats_kernel<<<MTOT / 128, 256>>>(ph);
    bn_finalize_kernel<<<(MTOT * DE) / 4 / 256, 256>>>(ph, x, gamma, beta, out);
}